// round 16
// baseline (speedup 1.0000x reference)
#include <cuda_runtime.h>

// ---------------------------------------------------------------------------
// GAT returning only h[N-1]: cone pruning, single persistent kernel.
// R16 = R13 base (best-tied: 36.96us) + ONE change: gsync arrival uses a
// RACE-FREE two-level atomic tree with MONOTONIC counters (no resets in the
// barrier path; block 0 zeroes them in the P5 epilogue for graph replay).
// R14's version deadlocked: plain-store counter reset raced next-gen arrivals.
// ---------------------------------------------------------------------------

#define NB       148        // 1 block per SM -> guaranteed co-resident
#define NT       512
#define SCAN_U   4
#define MAX_S2   512
#define MAX_U2   512
#define MAX_U1   8192
#define MAX_E1   16384
#define MAXD     512
#define NFLAG    131072
#define BMWORDS  4096
#define P3SLOTS  (NB * 4)   // 592 node slots per round
#define NGRP     8          // barrier arrival groups (4 of 19, 4 of 18)

__device__ int   d_flag1[NFLAG], d_flag2[NFLAG];
__device__ int   d_idx1[NFLAG],  d_idx2[NFLAG];
__device__ int   d_s2src[MAX_S2];
__device__ int   d_uniq2[MAX_U2];
__device__ int   d_uniq1[MAX_U1];
__device__ int   d_e1src[MAX_E1], d_e1dst[MAX_E1];
__device__ int   d_cnt[4];                 // 0:n_s2 1:n_u2 2:n_e1 3:n_u1
__device__ float d_h0[MAX_U1 * 64];
__device__ float d_as1[MAX_U1 * 2], d_ad1[MAX_U1 * 2];
__device__ float d_ht2[MAX_U2 * 128];
__device__ float d_as2[MAX_U2 * 2], d_ad2[MAX_U2 * 2];
__device__ volatile int d_bar_gen;
__device__ int   d_bar_grp[NGRP * 32];     // monotonic; one per 128B line
__device__ int   d_bar_root;               // monotonic

__device__ __forceinline__ float lrelu(float x, float s) {
    return x > 0.f ? x : s * x;
}

__device__ __forceinline__ void add_uniq2(int u) {
    if (atomicCAS(&d_flag2[u], 0, 1) == 0) {
        int p = atomicAdd(&d_cnt[1], 1);
        if (p < MAX_U2) { d_uniq2[p] = u; d_idx2[u] = p; }
    }
}
__device__ __forceinline__ void add_uniq1(int u) {
    if (atomicCAS(&d_flag1[u], 0, 1) == 0) {
        int p = atomicAdd(&d_cnt[3], 1);
        if (p < MAX_U1) { d_uniq1[p] = u; d_idx1[u] = p; }
    }
}

// grid-wide barrier, generation G = 1,2,3,4 (monotonic counters, race-free)
__device__ __forceinline__ void gsync(int G) {
    __syncthreads();
    if (threadIdx.x == 0) {
        __threadfence();
        int grp = blockIdx.x & (NGRP - 1);
        int gsize = (grp < 4) ? 19 : 18;           // 4*19 + 4*18 = 148
        bool release = false;
        if (atomicAdd(&d_bar_grp[grp * 32], 1) == G * gsize - 1) {
            if (atomicAdd(&d_bar_root, 1) == G * NGRP - 1) {
                __threadfence();
                d_bar_gen = G;
                release = true;
            }
        }
        if (!release) {
            while (d_bar_gen < G) { __nanosleep(32); }
        }
        __threadfence();
    }
    __syncthreads();
}

__device__ __forceinline__ void p1_hit(const int* ei, int e) {
    int s = ei[e];
    int p = atomicAdd(&d_cnt[0], 1);
    if (p < MAX_S2) d_s2src[p] = s;
    add_uniq2(s); add_uniq1(s);
}
__device__ __forceinline__ void p2_hit(const int* ei, int e, int d) {
    int s = ei[e];
    int p = atomicAdd(&d_cnt[2], 1);
    if (p < MAX_E1) { d_e1src[p] = s; d_e1dst[p] = d; }
    add_uniq1(s);
}

__device__ __forceinline__ float wredsum(float v) {
    #pragma unroll
    for (int o = 16; o > 0; o >>= 1) v += __shfl_xor_sync(0xffffffffu, v, o);
    return v;
}
__device__ __forceinline__ float wredmax(float v) {
    #pragma unroll
    for (int o = 16; o > 0; o >>= 1) v = fmaxf(v, __shfl_xor_sync(0xffffffffu, v, o));
    return v;
}

__global__ void __launch_bounds__(NT, 1)
gat_fused(const float* __restrict__ x,   const int* __restrict__ ei,
          const float* __restrict__ W1,  const float* __restrict__ asrc1,
          const float* __restrict__ adst1, const float* __restrict__ b1,
          const float* __restrict__ g1,  const float* __restrict__ be1,
          const float* __restrict__ mn1, const float* __restrict__ vr1,
          const float* __restrict__ W2,  const float* __restrict__ asrc2,
          const float* __restrict__ adst2, const float* __restrict__ b2,
          const float* __restrict__ g2,  const float* __restrict__ be2,
          const float* __restrict__ mn2, const float* __restrict__ vr2,
          const float* __restrict__ fcW, const float* __restrict__ fcb,
          float* __restrict__ out, int E, int target)
{
    __shared__ unsigned s_bm[BMWORDS];               // 16 KB (P2)
    __shared__ int   s_si[MAXD + 8];
    __shared__ float s_a0[MAXD + 8], s_a1[MAXD + 8];
    __shared__ float s_x4[512], part[NT], hs[128];   // P3: 4 node rows
    __shared__ float ss[4], sd[4];
    __shared__ float s_inv0, s_inv1;
    __shared__ int   s_scnt;

    const int tid  = threadIdx.x;
    const int lane = tid & 31;
    const int gtid = blockIdx.x * NT + tid;
    const int gstr = NB * NT;
    const int* dstp = ei + E;
    const int n4 = E >> 2;
    const int4* d4 = (const int4*)dstp;

    // ---------------- P1: edges into TARGET ---------------------------------
    if (gtid == 0) { add_uniq2(target); add_uniq1(target); }
    {
        for (int base = gtid; base < n4; base += gstr * SCAN_U) {
            int4 v[SCAN_U]; int idx[SCAN_U];
            #pragma unroll
            for (int u = 0; u < SCAN_U; u++) {
                idx[u] = base + u * gstr;
                v[u] = (idx[u] < n4) ? d4[idx[u]] : make_int4(-1, -1, -1, -1);
            }
            #pragma unroll
            for (int u = 0; u < SCAN_U; u++) {
                int i = idx[u];
                if (v[u].x == target) p1_hit(ei, 4*i+0);
                if (v[u].y == target) p1_hit(ei, 4*i+1);
                if (v[u].z == target) p1_hit(ei, 4*i+2);
                if (v[u].w == target) p1_hit(ei, 4*i+3);
            }
        }
        for (int e = (n4 << 2) + gtid; e < E; e += gstr)
            if (dstp[e] == target) p1_hit(ei, e);
    }
    gsync(1);

    // ---------------- P2: edges into uniq2 (shared bitmap) ------------------
    {
        for (int w = tid; w < BMWORDS; w += NT) s_bm[w] = 0u;
        __syncthreads();
        int n2 = min(d_cnt[1], MAX_U2);
        for (int t = tid; t < n2; t += NT) {
            int u = d_uniq2[t];
            atomicOr(&s_bm[u >> 5], 1u << (u & 31));
        }
        __syncthreads();
        for (int base = gtid; base < n4; base += gstr * SCAN_U) {
            int4 v[SCAN_U]; int idx[SCAN_U];
            #pragma unroll
            for (int u = 0; u < SCAN_U; u++) {
                idx[u] = base + u * gstr;
                v[u] = (idx[u] < n4) ? d4[idx[u]] : make_int4(-1, -1, -1, -1);
            }
            #pragma unroll
            for (int u = 0; u < SCAN_U; u++) {
                int i = idx[u];
                int dx = v[u].x, dy = v[u].y, dz = v[u].z, dw = v[u].w;
                if (dx >= 0 && ((s_bm[dx >> 5] >> (dx & 31)) & 1u)) p2_hit(ei, 4*i+0, dx);
                if (dy >= 0 && ((s_bm[dy >> 5] >> (dy & 31)) & 1u)) p2_hit(ei, 4*i+1, dy);
                if (dz >= 0 && ((s_bm[dz >> 5] >> (dz & 31)) & 1u)) p2_hit(ei, 4*i+2, dz);
                if (dw >= 0 && ((s_bm[dw >> 5] >> (dw & 31)) & 1u)) p2_hit(ei, 4*i+3, dw);
            }
        }
        for (int e = (n4 << 2) + gtid; e < E; e += gstr) {
            int d = dstp[e];
            if ((s_bm[d >> 5] >> (d & 31)) & 1u) p2_hit(ei, e, d);
        }
    }
    gsync(2);

    // snapshot counters (stable from here on)
    const int ns2 = min(d_cnt[0], MAX_S2);
    const int nu2 = min(d_cnt[1], MAX_U2);
    const int ne1 = min(d_cnt[2], MAX_E1);
    const int nu1 = min(d_cnt[3], MAX_U1);

    // ---------------- P3: h0 = x@W1, 4 nodes/block (R13) --------------------
    {
        int grp = tid >> 7;          // 0..3   node group within block
        int gt  = tid & 127;         // 0..127 thread within group
        int j   = gt & 63;           // output dim
        int kq  = gt >> 6;           // 0..1   k-slice (64 k's each)
        float* gx = &s_x4[grp * 128];
        int rounds = (nu1 + P3SLOTS - 1) / P3SLOTS;   // 1 for nu1 <= 592
        for (int r = 0; r < rounds; r++) {
            int ui = r * P3SLOTS + blockIdx.x * 4 + grp;
            bool act = (ui < nu1);
            if (act) {
                int u = d_uniq1[ui];
                gx[gt] = x[(size_t)u * 128 + gt];
            }
            __syncthreads();
            float acc0 = 0.f, acc1 = 0.f;
            if (act) {
                #pragma unroll
                for (int k = 0; k < 64; k += 2) {
                    acc0 = fmaf(gx[kq * 64 + k],     W1[(kq * 64 + k) * 64 + j],     acc0);
                    acc1 = fmaf(gx[kq * 64 + k + 1], W1[(kq * 64 + k + 1) * 64 + j], acc1);
                }
            }
            part[tid] = acc0 + acc1;
            __syncthreads();
            if (act && gt < 64) {
                float h = part[grp * 128 + j] + part[grp * 128 + 64 + j];
                d_h0[ui * 64 + j] = h;
                float vs = h * asrc1[j];
                float vd = h * adst1[j];
                #pragma unroll
                for (int o = 16; o > 0; o >>= 1) {
                    vs += __shfl_xor_sync(0xffffffffu, vs, o);
                    vd += __shfl_xor_sync(0xffffffffu, vd, o);
                }
                if ((j & 31) == 0) {
                    int hh = j >> 5;
                    d_as1[ui * 2 + hh] = vs;
                    d_ad1[ui * 2 + hh] = vd;
                }
            }
            __syncthreads();
        }
    }
    gsync(3);

    // ---------------- P4: layer-1 GAT + projection per uniq2 node -----------
    {
        for (int vi = blockIdx.x; vi < nu2; vi += NB) {
            int vnode = d_uniq2[vi];
            int vIdx  = d_idx1[vnode];
            if (tid == 0) { s_scnt = 1; s_si[0] = vIdx; }   // self loop
            __syncthreads();
            for (int i = tid; i < ne1; i += NT) {
                if (d_e1dst[i] == vnode) {
                    int p = atomicAdd(&s_scnt, 1);
                    if (p < MAXD) s_si[p] = d_idx1[d_e1src[i]];
                }
            }
            __syncthreads();
            int cnt = min(s_scnt, MAXD);
            if (tid < 32) {                       // warp-0 shfl softmax (R10)
                float ad0 = d_ad1[vIdx * 2 + 0];
                float ad1 = d_ad1[vIdx * 2 + 1];
                float lm0 = -1e30f, lm1 = -1e30f;
                for (int k = lane; k < cnt; k += 32) {
                    int si = s_si[k];
                    float e0 = lrelu(d_as1[si * 2 + 0] + ad0, 0.2f);
                    float e1 = lrelu(d_as1[si * 2 + 1] + ad1, 0.2f);
                    s_a0[k] = e0; s_a1[k] = e1;
                    lm0 = fmaxf(lm0, e0); lm1 = fmaxf(lm1, e1);
                }
                float m0 = wredmax(lm0), m1 = wredmax(lm1);
                float ls0 = 0.f, ls1 = 0.f;
                for (int k = lane; k < cnt; k += 32) {
                    float a0 = __expf(s_a0[k] - m0);
                    float a1 = __expf(s_a1[k] - m1);
                    s_a0[k] = a0; s_a1[k] = a1;
                    ls0 += a0; ls1 += a1;
                }
                float sum0 = wredsum(ls0), sum1 = wredsum(ls1);
                if (lane == 0) {
                    s_inv0 = 1.f / (sum0 + 1e-16f);
                    s_inv1 = 1.f / (sum1 + 1e-16f);
                }
            }
            __syncthreads();
            if (tid < 64) {
                int j = tid;
                const float* sa = (j >= 32) ? s_a1 : s_a0;
                float inv = (j >= 32) ? s_inv1 : s_inv0;
                float acc = 0.f;
                for (int k = 0; k < cnt; k++)
                    acc = fmaf(sa[k], d_h0[s_si[k] * 64 + j], acc);
                acc *= inv;
                float o = acc + b1[j];
                o = lrelu(o, 0.01f);
                o = (o - mn1[j]) * rsqrtf(vr1[j] + 1e-5f) * g1[j] + be1[j];
                hs[j] = o;
            }
            __syncthreads();
            if (tid < 128) {
                int j = tid;
                float acc = 0.f;
                #pragma unroll
                for (int k = 0; k < 64; k++) acc = fmaf(hs[k], W2[k * 128 + j], acc);
                d_ht2[vi * 128 + j] = acc;
                float vs = wredsum(acc * asrc2[j]);
                float vd = wredsum(acc * adst2[j]);
                int w = j >> 5;
                if ((j & 31) == 0) { ss[w] = vs; sd[w] = vd; }
            }
            __syncthreads();
            if (tid == 0) {
                d_as2[vi * 2 + 0] = ss[0] + ss[1];
                d_as2[vi * 2 + 1] = ss[2] + ss[3];
                d_ad2[vi * 2 + 0] = sd[0] + sd[1];
                d_ad2[vi * 2 + 1] = sd[2] + sd[3];
            }
            __syncthreads();
        }
    }
    gsync(4);

    // ---------------- P5 (block 0): layer-2 at TARGET + FC + cleanup --------
    if (blockIdx.x != 0) return;
    {
        int cnt = ns2 + 1;                       // + self loop
        if (tid < 32) {                          // warp-0 shfl softmax (R10)
            int u_t = d_idx2[target];
            float ad0 = d_ad2[u_t * 2 + 0];
            float ad1 = d_ad2[u_t * 2 + 1];
            float lm0 = -1e30f, lm1 = -1e30f;
            for (int k = lane; k < cnt; k += 32) {
                int src = (k == ns2) ? target : d_s2src[k];
                int si = d_idx2[src];
                s_si[k] = si;
                float e0 = lrelu(d_as2[si * 2 + 0] + ad0, 0.2f);
                float e1 = lrelu(d_as2[si * 2 + 1] + ad1, 0.2f);
                s_a0[k] = e0; s_a1[k] = e1;
                lm0 = fmaxf(lm0, e0); lm1 = fmaxf(lm1, e1);
            }
            float m0 = wredmax(lm0), m1 = wredmax(lm1);
            float ls0 = 0.f, ls1 = 0.f;
            for (int k = lane; k < cnt; k += 32) {
                float a0 = __expf(s_a0[k] - m0);
                float a1 = __expf(s_a1[k] - m1);
                s_a0[k] = a0; s_a1[k] = a1;
                ls0 += a0; ls1 += a1;
            }
            float sum0 = wredsum(ls0), sum1 = wredsum(ls1);
            if (lane == 0) {
                s_inv0 = 1.f / (sum0 + 1e-16f);
                s_inv1 = 1.f / (sum1 + 1e-16f);
            }
        }
        __syncthreads();
        if (tid < 128) {
            int j = tid;
            const float* sa = (j >= 64) ? s_a1 : s_a0;
            float inv = (j >= 64) ? s_inv1 : s_inv0;
            float acc = 0.f;
            for (int k = 0; k < cnt; k++)
                acc = fmaf(sa[k], d_ht2[s_si[k] * 128 + j], acc);
            acc *= inv;
            float o = acc + b2[j];
            o = lrelu(o, 0.01f);
            o = (o - mn2[j]) * rsqrtf(vr2[j] + 1e-5f) * g2[j] + be2[j];
            hs[j] = o;
        }
        __syncthreads();
        if (tid < 60) {
            float r = fcb[tid];
            #pragma unroll 4
            for (int q = 0; q < 128; q++) r = fmaf(hs[q], fcW[q * 60 + tid], r);
            out[tid] = r;
        }
        // cleanup for next graph replay (after out[] written).
        // All barrier arrivals for gens 1..4 happened-before gsync(4)'s
        // release, so zeroing the monotonic counters here is race-free.
        __syncthreads();
        for (int i = tid; i < nu1; i += NT) d_flag1[d_uniq1[i]] = 0;
        for (int i = tid; i < nu2; i += NT) d_flag2[d_uniq2[i]] = 0;
        if (tid < NGRP) d_bar_grp[tid * 32] = 0;
        if (tid == 0) { d_bar_root = 0; d_bar_gen = 0; }
        __syncthreads();
        if (tid < 4) d_cnt[tid] = 0;
    }
}

// ---------------------------------------------------------------------------
extern "C" void kernel_launch(void* const* d_in, const int* in_sizes, int n_in,
                              void* d_out, int out_size) {
    const float* x      = (const float*)d_in[0];
    const int*   ei     = (const int*)d_in[1];     // int32 (JAX x64 disabled)
    const float* W1     = (const float*)d_in[2];
    const float* asrc1  = (const float*)d_in[3];
    const float* adst1  = (const float*)d_in[4];
    const float* b1     = (const float*)d_in[5];
    const float* g1     = (const float*)d_in[6];
    const float* be1    = (const float*)d_in[7];
    const float* mn1    = (const float*)d_in[8];
    const float* vr1    = (const float*)d_in[9];
    const float* W2     = (const float*)d_in[10];
    const float* asrc2  = (const float*)d_in[11];
    const float* adst2  = (const float*)d_in[12];
    const float* b2     = (const float*)d_in[13];
    const float* g2     = (const float*)d_in[14];
    const float* be2    = (const float*)d_in[15];
    const float* mn2    = (const float*)d_in[16];
    const float* vr2    = (const float*)d_in[17];
    const float* fcW    = (const float*)d_in[18];
    const float* fcb    = (const float*)d_in[19];
    float*       out    = (float*)d_out;

    int N = in_sizes[0] / 128;
    int E = in_sizes[1] / 2;
    int target = N - 1;

    gat_fused<<<NB, NT>>>(x, ei, W1, asrc1, adst1, b1, g1, be1, mn1, vr1,
                          W2, asrc2, adst2, b2, g2, be2, mn2, vr2, fcW, fcb,
                          out, E, target);
}

// round 17
// speedup vs baseline: 1.0828x; 1.0828x over previous
#include <cuda_runtime.h>

// ---------------------------------------------------------------------------
// GAT returning only h[N-1]: cone pruning, single persistent kernel.
// R17 = R13 base (best-tied: 36.96us, R6 single-counter barrier) + ONE
// mechanism change: P2 writes a per-destination adjacency list directly
// (slot = d_idx2[dst], stable after barrier 1), so P4's per-node edge-match
// re-scan (290-int global read + smem atomics + 2 bars) is eliminated.
// ---------------------------------------------------------------------------

#define NB       148        // 1 block per SM -> guaranteed co-resident
#define NT       512
#define SCAN_U   4
#define MAX_S2   512
#define MAX_U2   512
#define MAX_U1   8192
#define MAXDW    128        // per-destination adjacency cap (Poisson(16))
#define NFLAG    131072
#define BMWORDS  4096
#define P3SLOTS  (NB * 4)   // 592 node slots per round

__device__ int   d_flag1[NFLAG], d_flag2[NFLAG];
__device__ int   d_idx1[NFLAG],  d_idx2[NFLAG];
__device__ int   d_s2src[MAX_S2];
__device__ int   d_uniq2[MAX_U2];
__device__ int   d_uniq1[MAX_U1];
__device__ int   d_adj[MAX_U2 * MAXDW];    // per-uniq2-slot source lists
__device__ int   d_deg[MAX_U2];
__device__ int   d_cnt[4];                 // 0:n_s2 1:n_u2 2:(unused) 3:n_u1
__device__ float d_h0[MAX_U1 * 64];
__device__ float d_as1[MAX_U1 * 2], d_ad1[MAX_U1 * 2];
__device__ float d_ht2[MAX_U2 * 128];
__device__ float d_as2[MAX_U2 * 2], d_ad2[MAX_U2 * 2];
__device__ volatile int d_bar_gen;
__device__ int   d_bar_cnt;

__device__ __forceinline__ float lrelu(float x, float s) {
    return x > 0.f ? x : s * x;
}

__device__ __forceinline__ void add_uniq2(int u) {
    if (atomicCAS(&d_flag2[u], 0, 1) == 0) {
        int p = atomicAdd(&d_cnt[1], 1);
        if (p < MAX_U2) { d_uniq2[p] = u; d_idx2[u] = p; }
    }
}
__device__ __forceinline__ void add_uniq1(int u) {
    if (atomicCAS(&d_flag1[u], 0, 1) == 0) {
        int p = atomicAdd(&d_cnt[3], 1);
        if (p < MAX_U1) { d_uniq1[p] = u; d_idx1[u] = p; }
    }
}

// grid-wide barrier (R6 single-counter version, empirically best)
__device__ __forceinline__ void gsync() {
    __syncthreads();
    if (threadIdx.x == 0) {
        __threadfence();
        int g = d_bar_gen;
        if (atomicAdd(&d_bar_cnt, 1) == NB - 1) {
            d_bar_cnt = 0;
            __threadfence();
            d_bar_gen = g + 1;
        } else {
            while (d_bar_gen == g) { __nanosleep(32); }
        }
        __threadfence();
    }
    __syncthreads();
}

__device__ __forceinline__ void p1_hit(const int* ei, int e) {
    int s = ei[e];
    int p = atomicAdd(&d_cnt[0], 1);
    if (p < MAX_S2) d_s2src[p] = s;
    add_uniq2(s); add_uniq1(s);
}
// P2 hit: append src to dst's adjacency slot (d_idx2 stable after barrier 1)
__device__ __forceinline__ void p2_hit(const int* ei, int e, int d) {
    int s = ei[e];
    int slot = d_idx2[d];
    int p = atomicAdd(&d_deg[slot], 1);
    if (p < MAXDW) d_adj[slot * MAXDW + p] = s;
    add_uniq1(s);
}

__device__ __forceinline__ float wredsum(float v) {
    #pragma unroll
    for (int o = 16; o > 0; o >>= 1) v += __shfl_xor_sync(0xffffffffu, v, o);
    return v;
}
__device__ __forceinline__ float wredmax(float v) {
    #pragma unroll
    for (int o = 16; o > 0; o >>= 1) v = fmaxf(v, __shfl_xor_sync(0xffffffffu, v, o));
    return v;
}

__global__ void __launch_bounds__(NT, 1)
gat_fused(const float* __restrict__ x,   const int* __restrict__ ei,
          const float* __restrict__ W1,  const float* __restrict__ asrc1,
          const float* __restrict__ adst1, const float* __restrict__ b1,
          const float* __restrict__ g1,  const float* __restrict__ be1,
          const float* __restrict__ mn1, const float* __restrict__ vr1,
          const float* __restrict__ W2,  const float* __restrict__ asrc2,
          const float* __restrict__ adst2, const float* __restrict__ b2,
          const float* __restrict__ g2,  const float* __restrict__ be2,
          const float* __restrict__ mn2, const float* __restrict__ vr2,
          const float* __restrict__ fcW, const float* __restrict__ fcb,
          float* __restrict__ out, int E, int target)
{
    __shared__ unsigned s_bm[BMWORDS];               // 16 KB (P2)
    __shared__ int   s_si[MAXDW + MAX_S2 + 8];
    __shared__ float s_a0[MAX_S2 + 8], s_a1[MAX_S2 + 8];
    __shared__ float s_x4[512], part[NT], hs[128];   // P3: 4 node rows
    __shared__ float ss[4], sd[4];
    __shared__ float s_inv0, s_inv1;

    const int tid  = threadIdx.x;
    const int lane = tid & 31;
    const int gtid = blockIdx.x * NT + tid;
    const int gstr = NB * NT;
    const int* dstp = ei + E;
    const int n4 = E >> 2;
    const int4* d4 = (const int4*)dstp;

    // ---------------- P1: edges into TARGET (+ zero d_deg) ------------------
    if (gtid == 0) { add_uniq2(target); add_uniq1(target); }
    for (int i = gtid; i < MAX_U2; i += gstr) d_deg[i] = 0;
    {
        for (int base = gtid; base < n4; base += gstr * SCAN_U) {
            int4 v[SCAN_U]; int idx[SCAN_U];
            #pragma unroll
            for (int u = 0; u < SCAN_U; u++) {
                idx[u] = base + u * gstr;
                v[u] = (idx[u] < n4) ? d4[idx[u]] : make_int4(-1, -1, -1, -1);
            }
            #pragma unroll
            for (int u = 0; u < SCAN_U; u++) {
                int i = idx[u];
                if (v[u].x == target) p1_hit(ei, 4*i+0);
                if (v[u].y == target) p1_hit(ei, 4*i+1);
                if (v[u].z == target) p1_hit(ei, 4*i+2);
                if (v[u].w == target) p1_hit(ei, 4*i+3);
            }
        }
        for (int e = (n4 << 2) + gtid; e < E; e += gstr)
            if (dstp[e] == target) p1_hit(ei, e);
    }
    gsync();

    // ---------------- P2: edges into uniq2 -> adjacency lists ---------------
    {
        for (int w = tid; w < BMWORDS; w += NT) s_bm[w] = 0u;
        __syncthreads();
        int n2 = min(d_cnt[1], MAX_U2);
        for (int t = tid; t < n2; t += NT) {
            int u = d_uniq2[t];
            atomicOr(&s_bm[u >> 5], 1u << (u & 31));
        }
        __syncthreads();
        for (int base = gtid; base < n4; base += gstr * SCAN_U) {
            int4 v[SCAN_U]; int idx[SCAN_U];
            #pragma unroll
            for (int u = 0; u < SCAN_U; u++) {
                idx[u] = base + u * gstr;
                v[u] = (idx[u] < n4) ? d4[idx[u]] : make_int4(-1, -1, -1, -1);
            }
            #pragma unroll
            for (int u = 0; u < SCAN_U; u++) {
                int i = idx[u];
                int dx = v[u].x, dy = v[u].y, dz = v[u].z, dw = v[u].w;
                if (dx >= 0 && ((s_bm[dx >> 5] >> (dx & 31)) & 1u)) p2_hit(ei, 4*i+0, dx);
                if (dy >= 0 && ((s_bm[dy >> 5] >> (dy & 31)) & 1u)) p2_hit(ei, 4*i+1, dy);
                if (dz >= 0 && ((s_bm[dz >> 5] >> (dz & 31)) & 1u)) p2_hit(ei, 4*i+2, dz);
                if (dw >= 0 && ((s_bm[dw >> 5] >> (dw & 31)) & 1u)) p2_hit(ei, 4*i+3, dw);
            }
        }
        for (int e = (n4 << 2) + gtid; e < E; e += gstr) {
            int d = dstp[e];
            if ((s_bm[d >> 5] >> (d & 31)) & 1u) p2_hit(ei, e, d);
        }
    }
    gsync();

    // snapshot counters (stable from here on)
    const int ns2 = min(d_cnt[0], MAX_S2);
    const int nu2 = min(d_cnt[1], MAX_U2);
    const int nu1 = min(d_cnt[3], MAX_U1);

    // ---------------- P3: h0 = x@W1, 4 nodes/block (R13) --------------------
    {
        int grp = tid >> 7;          // 0..3   node group within block
        int gt  = tid & 127;         // 0..127 thread within group
        int j   = gt & 63;           // output dim
        int kq  = gt >> 6;           // 0..1   k-slice (64 k's each)
        float* gx = &s_x4[grp * 128];
        int rounds = (nu1 + P3SLOTS - 1) / P3SLOTS;   // 1 for nu1 <= 592
        for (int r = 0; r < rounds; r++) {
            int ui = r * P3SLOTS + blockIdx.x * 4 + grp;
            bool act = (ui < nu1);
            if (act) {
                int u = d_uniq1[ui];
                gx[gt] = x[(size_t)u * 128 + gt];
            }
            __syncthreads();
            float acc0 = 0.f, acc1 = 0.f;
            if (act) {
                #pragma unroll
                for (int k = 0; k < 64; k += 2) {
                    acc0 = fmaf(gx[kq * 64 + k],     W1[(kq * 64 + k) * 64 + j],     acc0);
                    acc1 = fmaf(gx[kq * 64 + k + 1], W1[(kq * 64 + k + 1) * 64 + j], acc1);
                }
            }
            part[tid] = acc0 + acc1;
            __syncthreads();
            if (act && gt < 64) {
                float h = part[grp * 128 + j] + part[grp * 128 + 64 + j];
                d_h0[ui * 64 + j] = h;
                float vs = h * asrc1[j];
                float vd = h * adst1[j];
                #pragma unroll
                for (int o = 16; o > 0; o >>= 1) {
                    vs += __shfl_xor_sync(0xffffffffu, vs, o);
                    vd += __shfl_xor_sync(0xffffffffu, vd, o);
                }
                if ((j & 31) == 0) {
                    int hh = j >> 5;
                    d_as1[ui * 2 + hh] = vs;
                    d_ad1[ui * 2 + hh] = vd;
                }
            }
            __syncthreads();
        }
    }
    gsync();

    // ---------------- P4: layer-1 GAT + projection per uniq2 node -----------
    {
        for (int vi = blockIdx.x; vi < nu2; vi += NB) {
            int vnode = d_uniq2[vi];
            int vIdx  = d_idx1[vnode];
            // CHANGED vs R13: direct adjacency gather (no edge re-scan)
            int deg = min(d_deg[vi], MAXDW);
            int cnt = deg + 1;                          // + self loop
            for (int i = tid; i < deg; i += NT)
                s_si[i] = d_idx1[d_adj[vi * MAXDW + i]];
            if (tid == 0) s_si[deg] = vIdx;
            __syncthreads();
            if (tid < 32) {                       // warp-0 shfl softmax (R10)
                float ad0 = d_ad1[vIdx * 2 + 0];
                float ad1 = d_ad1[vIdx * 2 + 1];
                float lm0 = -1e30f, lm1 = -1e30f;
                for (int k = lane; k < cnt; k += 32) {
                    int si = s_si[k];
                    float e0 = lrelu(d_as1[si * 2 + 0] + ad0, 0.2f);
                    float e1 = lrelu(d_as1[si * 2 + 1] + ad1, 0.2f);
                    s_a0[k] = e0; s_a1[k] = e1;
                    lm0 = fmaxf(lm0, e0); lm1 = fmaxf(lm1, e1);
                }
                float m0 = wredmax(lm0), m1 = wredmax(lm1);
                float ls0 = 0.f, ls1 = 0.f;
                for (int k = lane; k < cnt; k += 32) {
                    float a0 = __expf(s_a0[k] - m0);
                    float a1 = __expf(s_a1[k] - m1);
                    s_a0[k] = a0; s_a1[k] = a1;
                    ls0 += a0; ls1 += a1;
                }
                float sum0 = wredsum(ls0), sum1 = wredsum(ls1);
                if (lane == 0) {
                    s_inv0 = 1.f / (sum0 + 1e-16f);
                    s_inv1 = 1.f / (sum1 + 1e-16f);
                }
            }
            __syncthreads();
            if (tid < 64) {
                int j = tid;
                const float* sa = (j >= 32) ? s_a1 : s_a0;
                float inv = (j >= 32) ? s_inv1 : s_inv0;
                float acc = 0.f;
                for (int k = 0; k < cnt; k++)
                    acc = fmaf(sa[k], d_h0[s_si[k] * 64 + j], acc);
                acc *= inv;
                float o = acc + b1[j];
                o = lrelu(o, 0.01f);
                o = (o - mn1[j]) * rsqrtf(vr1[j] + 1e-5f) * g1[j] + be1[j];
                hs[j] = o;
            }
            __syncthreads();
            if (tid < 128) {
                int j = tid;
                float acc = 0.f;
                #pragma unroll
                for (int k = 0; k < 64; k++) acc = fmaf(hs[k], W2[k * 128 + j], acc);
                d_ht2[vi * 128 + j] = acc;
                float vs = wredsum(acc * asrc2[j]);
                float vd = wredsum(acc * adst2[j]);
                int w = j >> 5;
                if ((j & 31) == 0) { ss[w] = vs; sd[w] = vd; }
            }
            __syncthreads();
            if (tid == 0) {
                d_as2[vi * 2 + 0] = ss[0] + ss[1];
                d_as2[vi * 2 + 1] = ss[2] + ss[3];
                d_ad2[vi * 2 + 0] = sd[0] + sd[1];
                d_ad2[vi * 2 + 1] = sd[2] + sd[3];
            }
            __syncthreads();
        }
    }
    gsync();

    // ---------------- P5 (block 0): layer-2 at TARGET + FC + cleanup --------
    if (blockIdx.x != 0) return;
    {
        int cnt = ns2 + 1;                       // + self loop
        if (tid < 32) {                          // warp-0 shfl softmax (R10)
            int u_t = d_idx2[target];
            float ad0 = d_ad2[u_t * 2 + 0];
            float ad1 = d_ad2[u_t * 2 + 1];
            float lm0 = -1e30f, lm1 = -1e30f;
            for (int k = lane; k < cnt; k += 32) {
                int src = (k == ns2) ? target : d_s2src[k];
                int si = d_idx2[src];
                s_si[k] = si;
                float e0 = lrelu(d_as2[si * 2 + 0] + ad0, 0.2f);
                float e1 = lrelu(d_as2[si * 2 + 1] + ad1, 0.2f);
                s_a0[k] = e0; s_a1[k] = e1;
                lm0 = fmaxf(lm0, e0); lm1 = fmaxf(lm1, e1);
            }
            float m0 = wredmax(lm0), m1 = wredmax(lm1);
            float ls0 = 0.f, ls1 = 0.f;
            for (int k = lane; k < cnt; k += 32) {
                float a0 = __expf(s_a0[k] - m0);
                float a1 = __expf(s_a1[k] - m1);
                s_a0[k] = a0; s_a1[k] = a1;
                ls0 += a0; ls1 += a1;
            }
            float sum0 = wredsum(ls0), sum1 = wredsum(ls1);
            if (lane == 0) {
                s_inv0 = 1.f / (sum0 + 1e-16f);
                s_inv1 = 1.f / (sum1 + 1e-16f);
            }
        }
        __syncthreads();
        if (tid < 128) {
            int j = tid;
            const float* sa = (j >= 64) ? s_a1 : s_a0;
            float inv = (j >= 64) ? s_inv1 : s_inv0;
            float acc = 0.f;
            for (int k = 0; k < cnt; k++)
                acc = fmaf(sa[k], d_ht2[s_si[k] * 128 + j], acc);
            acc *= inv;
            float o = acc + b2[j];
            o = lrelu(o, 0.01f);
            o = (o - mn2[j]) * rsqrtf(vr2[j] + 1e-5f) * g2[j] + be2[j];
            hs[j] = o;
        }
        __syncthreads();
        if (tid < 60) {
            float r = fcb[tid];
            #pragma unroll 4
            for (int q = 0; q < 128; q++) r = fmaf(hs[q], fcW[q * 60 + tid], r);
            out[tid] = r;
        }
        // cleanup for next graph replay (after out[] written)
        __syncthreads();
        for (int i = tid; i < nu1; i += NT) d_flag1[d_uniq1[i]] = 0;
        for (int i = tid; i < nu2; i += NT) d_flag2[d_uniq2[i]] = 0;
        __syncthreads();
        if (tid < 4) d_cnt[tid] = 0;
    }
}

// ---------------------------------------------------------------------------
extern "C" void kernel_launch(void* const* d_in, const int* in_sizes, int n_in,
                              void* d_out, int out_size) {
    const float* x      = (const float*)d_in[0];
    const int*   ei     = (const int*)d_in[1];     // int32 (JAX x64 disabled)
    const float* W1     = (const float*)d_in[2];
    const float* asrc1  = (const float*)d_in[3];
    const float* adst1  = (const float*)d_in[4];
    const float* b1     = (const float*)d_in[5];
    const float* g1     = (const float*)d_in[6];
    const float* be1    = (const float*)d_in[7];
    const float* mn1    = (const float*)d_in[8];
    const float* vr1    = (const float*)d_in[9];
    const float* W2     = (const float*)d_in[10];
    const float* asrc2  = (const float*)d_in[11];
    const float* adst2  = (const float*)d_in[12];
    const float* b2     = (const float*)d_in[13];
    const float* g2     = (const float*)d_in[14];
    const float* be2    = (const float*)d_in[15];
    const float* mn2    = (const float*)d_in[16];
    const float* vr2    = (const float*)d_in[17];
    const float* fcW    = (const float*)d_in[18];
    const float* fcb    = (const float*)d_in[19];
    float*       out    = (float*)d_out;

    int N = in_sizes[0] / 128;
    int E = in_sizes[1] / 2;
    int target = N - 1;

    gat_fused<<<NB, NT>>>(x, ei, W1, asrc1, adst1, b1, g1, be1, mn1, vr1,
                          W2, asrc2, adst2, b2, g2, be2, mn2, vr2, fcW, fcb,
                          out, E, target);
}